// round 2
// baseline (speedup 1.0000x reference)
#include <cuda_runtime.h>
#include <math.h>
#include <float.h>

// Problem constants (shapes fixed by setup_inputs)
#define D_DIM 640
#define D4    160          // D_DIM / 4
#define S_SHOT 5
#define W_WAY  5
#define TOPK   8
#define M_MAX  50000

#define SIM_BLOCKS  592    // 4 blocks/SM * 148
#define SIM_THREADS 256
#define SIM_WARPS   (SIM_THREADS / 32)
#define NCAND       (SIM_BLOCKS * TOPK)   // candidates per way

// Static device scratch (no allocations allowed)
__device__ float g_q[W_WAY * D_DIM];          // mean of normalized support per way
__device__ float g_supv[W_WAY * S_SHOT];      // support self-similarities
__device__ float g_candv[W_WAY][NCAND];       // per-block top-8 candidates
__device__ int   g_candi[W_WAY][NCAND];

// ---------------------------------------------------------------------------
// Kernel 1: support norms -> q[w] = mean_s(support_hat[s,w]); support self-sims.
// ---------------------------------------------------------------------------
__global__ void prep_kernel(const float* __restrict__ sup) {
    __shared__ float s_inv[S_SHOT * W_WAY];
    __shared__ float s_q[W_WAY * D_DIM];
    int tid = threadIdx.x, wid = tid >> 5, lane = tid & 31;
    int nw = blockDim.x >> 5;

    // Phase 1: inverse norms of each support[s,w,:]
    for (int v = wid; v < S_SHOT * W_WAY; v += nw) {
        int s = v / W_WAY, w = v % W_WAY;
        const float* p = sup + (s * W_WAY + w) * D_DIM;
        float ss = 0.f;
        for (int i = lane; i < D_DIM; i += 32) { float x = p[i]; ss += x * x; }
        #pragma unroll
        for (int o = 16; o; o >>= 1) ss += __shfl_xor_sync(0xffffffffu, ss, o);
        if (lane == 0) s_inv[v] = 1.0f / fmaxf(sqrtf(ss), 1e-12f);
    }
    __syncthreads();

    // Phase 2: q[w][d]
    for (int i = tid; i < W_WAY * D_DIM; i += blockDim.x) {
        int w = i / D_DIM, d = i - w * D_DIM;
        float acc = 0.f;
        #pragma unroll
        for (int s = 0; s < S_SHOT; ++s)
            acc += sup[(s * W_WAY + w) * D_DIM + d] * s_inv[s * W_WAY + w];
        float qv = acc * (1.0f / (float)S_SHOT);
        s_q[i] = qv;
        g_q[i] = qv;
    }
    __syncthreads();

    // Phase 3: sim of q[w] with normalized support[m,w]
    for (int v = wid; v < W_WAY * S_SHOT; v += nw) {
        int w = v / S_SHOT, m = v % S_SHOT;
        const float* p = sup + (m * W_WAY + w) * D_DIM;
        float dpv = 0.f;
        for (int i = lane; i < D_DIM; i += 32) dpv += s_q[w * D_DIM + i] * p[i];
        #pragma unroll
        for (int o = 16; o; o >>= 1) dpv += __shfl_xor_sync(0xffffffffu, dpv, o);
        if (lane == 0) g_supv[w * S_SHOT + m] = dpv * s_inv[m * W_WAY + w];
    }
}

// ---------------------------------------------------------------------------
// Hot-path insertion into a register-resident sorted-8 (desc) list.
// Strictly-greater compare => earlier-seen (lower index) wins on ties.
// ---------------------------------------------------------------------------
#define INS(J) do {                                        \
    _Pragma("unroll")                                      \
    for (int kk = TOPK - 1; kk > (J); --kk) {              \
        av[kk] = av[kk - 1]; ai[kk] = ai[kk - 1];          \
    }                                                      \
    av[J] = x; ai[J] = i;                                  \
} while (0)

#define FILTER_INSERT() do {                                            \
    if (x > av[7]) {                                                    \
        if (x > av[3]) {                                                \
            if (x > av[1]) { if (x > av[0]) INS(0); else INS(1); }      \
            else           { if (x > av[2]) INS(2); else INS(3); }      \
        } else {                                                        \
            if (x > av[5]) { if (x > av[4]) INS(4); else INS(5); }      \
            else           { if (x > av[6]) INS(6); else INS(7); }      \
        }                                                               \
    }                                                                   \
} while (0)

// ---------------------------------------------------------------------------
// Kernel 2: the 128 MB pass, fused with per-way top-8 filtering.
// Each warp: 4 memory rows/group, butterfly reduce (all lanes get sums),
// lanes 0-4 keep a sorted-8 list for way==lane. Block merges warps' lists
// into 8 candidates per way, written to the global candidate buffer.
// ---------------------------------------------------------------------------
__global__ void __launch_bounds__(SIM_THREADS)
sim_kernel(const float* __restrict__ mem, int M) {
    __shared__ float4 s_q[W_WAY * D4];                       // 12.8 KB
    __shared__ float  s_cv[SIM_WARPS * W_WAY * TOPK];
    __shared__ int    s_ci[SIM_WARPS * W_WAY * TOPK];

    int tid = threadIdx.x;
    const float4* q4 = reinterpret_cast<const float4*>(g_q);
    for (int i = tid; i < W_WAY * D4; i += SIM_THREADS) s_q[i] = q4[i];
    __syncthreads();

    int wid = tid >> 5, lane = tid & 31;
    int nwarps = SIM_BLOCKS * SIM_WARPS;
    int gw = blockIdx.x * SIM_WARPS + wid;
    int groups = (M + 3) >> 2;
    // balanced contiguous partition: each warp gets floor or ceil, evenly spread
    int gbeg = (int)(((long long)gw * groups) / nwarps);
    int gend = (int)(((long long)(gw + 1) * groups) / nwarps);

    float av[TOPK]; int ai[TOPK];
    #pragma unroll
    for (int k = 0; k < TOPK; ++k) { av[k] = -FLT_MAX; ai[k] = 0x7fffffff; }

    const float4* base = reinterpret_cast<const float4*>(mem);

    for (int g = gbeg; g < gend; ++g) {
        int row0 = g << 2;
        // clamped row pointers (generic tail safety; M=50000 has no tail)
        const float4* p0 = base + (size_t)row0 * D4;
        const float4* p1 = base + (size_t)min(row0 + 1, M - 1) * D4;
        const float4* p2 = base + (size_t)min(row0 + 2, M - 1) * D4;
        const float4* p3 = base + (size_t)min(row0 + 3, M - 1) * D4;

        float ss0 = 0.f, ss1 = 0.f, ss2 = 0.f, ss3 = 0.f;
        float dp[W_WAY][4];
        #pragma unroll
        for (int w = 0; w < W_WAY; ++w) {
            dp[w][0] = 0.f; dp[w][1] = 0.f; dp[w][2] = 0.f; dp[w][3] = 0.f;
        }
        #pragma unroll
        for (int i = 0; i < 5; ++i) {
            int idx = lane + (i << 5);
            float4 v0 = p0[idx];
            float4 v1 = p1[idx];
            float4 v2 = p2[idx];
            float4 v3 = p3[idx];
            ss0 += v0.x * v0.x + v0.y * v0.y + v0.z * v0.z + v0.w * v0.w;
            ss1 += v1.x * v1.x + v1.y * v1.y + v1.z * v1.z + v1.w * v1.w;
            ss2 += v2.x * v2.x + v2.y * v2.y + v2.z * v2.z + v2.w * v2.w;
            ss3 += v3.x * v3.x + v3.y * v3.y + v3.z * v3.z + v3.w * v3.w;
            #pragma unroll
            for (int w = 0; w < W_WAY; ++w) {
                float4 a = s_q[w * D4 + idx];
                dp[w][0] += v0.x * a.x + v0.y * a.y + v0.z * a.z + v0.w * a.w;
                dp[w][1] += v1.x * a.x + v1.y * a.y + v1.z * a.z + v1.w * a.w;
                dp[w][2] += v2.x * a.x + v2.y * a.y + v2.z * a.z + v2.w * a.w;
                dp[w][3] += v3.x * a.x + v3.y * a.y + v3.z * a.z + v3.w * a.w;
            }
        }
        // butterfly reduce: every lane ends with the full sums
        #pragma unroll
        for (int o = 16; o; o >>= 1) {
            ss0 += __shfl_xor_sync(0xffffffffu, ss0, o);
            ss1 += __shfl_xor_sync(0xffffffffu, ss1, o);
            ss2 += __shfl_xor_sync(0xffffffffu, ss2, o);
            ss3 += __shfl_xor_sync(0xffffffffu, ss3, o);
            #pragma unroll
            for (int w = 0; w < W_WAY; ++w) {
                dp[w][0] += __shfl_xor_sync(0xffffffffu, dp[w][0], o);
                dp[w][1] += __shfl_xor_sync(0xffffffffu, dp[w][1], o);
                dp[w][2] += __shfl_xor_sync(0xffffffffu, dp[w][2], o);
                dp[w][3] += __shfl_xor_sync(0xffffffffu, dp[w][3], o);
            }
        }
        float i0 = 1.0f / fmaxf(sqrtf(ss0), 1e-12f);
        float i1 = 1.0f / fmaxf(sqrtf(ss1), 1e-12f);
        float i2 = 1.0f / fmaxf(sqrtf(ss2), 1e-12f);
        float i3 = 1.0f / fmaxf(sqrtf(ss3), 1e-12f);

        // lane w (w<5) filters way w; lanes >=5 see -FLT_MAX and never insert
        #define PICK(R) (lane == 0 ? dp[0][R] : lane == 1 ? dp[1][R] : \
                         lane == 2 ? dp[2][R] : lane == 3 ? dp[3][R] : \
                         lane == 4 ? dp[4][R] : -FLT_MAX)
        {
            float x; int i;
            x = (row0 + 0 < M) ? PICK(0) * i0 : -FLT_MAX; i = S_SHOT + row0 + 0; FILTER_INSERT();
            x = (row0 + 1 < M) ? PICK(1) * i1 : -FLT_MAX; i = S_SHOT + row0 + 1; FILTER_INSERT();
            x = (row0 + 2 < M) ? PICK(2) * i2 : -FLT_MAX; i = S_SHOT + row0 + 2; FILTER_INSERT();
            x = (row0 + 3 < M) ? PICK(3) * i3 : -FLT_MAX; i = S_SHOT + row0 + 3; FILTER_INSERT();
        }
        #undef PICK
    }

    // stash per-warp lists (lanes 0-4 only), sorted desc
    if (lane < W_WAY) {
        int b = (wid * W_WAY + lane) * TOPK;
        #pragma unroll
        for (int k = 0; k < TOPK; ++k) { s_cv[b + k] = av[k]; s_ci[b + k] = ai[k]; }
    }
    __syncthreads();

    // threads 0..4: merge the 8 warps' lists for way==tid (lists sorted desc,
    // warps scanned in ascending order => lower row index wins ties)
    if (tid < W_WAY) {
        int w = tid;
        float bv[TOPK]; int bi[TOPK];
        #pragma unroll
        for (int k = 0; k < TOPK; ++k) { bv[k] = -FLT_MAX; bi[k] = 0x7fffffff; }
        for (int j = 0; j < SIM_WARPS; ++j) {
            int b = (j * W_WAY + w) * TOPK;
            #pragma unroll
            for (int k = 0; k < TOPK; ++k) {
                float x = s_cv[b + k]; int i = s_ci[b + k];
                if (!(x > bv[7])) break;        // list sorted desc -> early out
                #pragma unroll
                for (int t = 0; t < TOPK; ++t) {
                    if (x > bv[t]) {
                        #pragma unroll
                        for (int u = TOPK - 1; u > t; --u) { bv[u] = bv[u-1]; bi[u] = bi[u-1]; }
                        bv[t] = x; bi[t] = i;
                        break;
                    }
                }
            }
        }
        int o = blockIdx.x * TOPK;
        #pragma unroll
        for (int k = 0; k < TOPK; ++k) { g_candv[w][o + k] = bv[k]; g_candi[w][o + k] = bi[k]; }
    }
}

// ---------------------------------------------------------------------------
// Kernel 3: per way -- merge candidates (+support sims) into global top-8
// with (value desc, index asc) ordering, then gather & weight the rows.
// ---------------------------------------------------------------------------
#define FT_THREADS 256

__device__ __forceinline__ bool better(float x, int i, float y, int j) {
    return (x > y) || (x == y && i < j);
}

__global__ void __launch_bounds__(FT_THREADS)
final_kernel(const float* __restrict__ sup, const float* __restrict__ mem,
             float* __restrict__ out) {
    __shared__ float sv[FT_THREADS * TOPK];
    __shared__ int   si[FT_THREADS * TOPK];
    int w = blockIdx.x;
    int tid = threadIdx.x;

    float av[TOPK]; int ai[TOPK];
    #pragma unroll
    for (int k = 0; k < TOPK; ++k) { av[k] = -FLT_MAX; ai[k] = 0x7fffffff; }

    for (int c = tid; c < NCAND; c += FT_THREADS) {
        float x = g_candv[w][c]; int i = g_candi[w][c];
        if (better(x, i, av[7], ai[7])) {
            #pragma unroll
            for (int t = 0; t < TOPK; ++t) {
                if (better(x, i, av[t], ai[t])) {
                    #pragma unroll
                    for (int u = TOPK - 1; u > t; --u) { av[u] = av[u-1]; ai[u] = ai[u-1]; }
                    av[t] = x; ai[t] = i;
                    break;
                }
            }
        }
    }
    if (tid == 0) {
        #pragma unroll
        for (int s = 0; s < S_SHOT; ++s) {
            float x = g_supv[w * S_SHOT + s]; int i = s;
            if (better(x, i, av[7], ai[7])) {
                #pragma unroll
                for (int t = 0; t < TOPK; ++t) {
                    if (better(x, i, av[t], ai[t])) {
                        #pragma unroll
                        for (int u = TOPK - 1; u > t; --u) { av[u] = av[u-1]; ai[u] = ai[u-1]; }
                        av[t] = x; ai[t] = i;
                        break;
                    }
                }
            }
        }
    }

    #pragma unroll
    for (int k = 0; k < TOPK; ++k) { sv[tid * TOPK + k] = av[k]; si[tid * TOPK + k] = ai[k]; }

    for (int stride = FT_THREADS >> 1; stride >= 1; stride >>= 1) {
        __syncthreads();
        if (tid < stride) {
            float la[TOPK], lb[TOPK], ov[TOPK];
            int   lia[TOPK], lib[TOPK], oi[TOPK];
            #pragma unroll
            for (int k = 0; k < TOPK; ++k) {
                la[k]  = sv[tid * TOPK + k];            lia[k] = si[tid * TOPK + k];
                lb[k]  = sv[(tid + stride) * TOPK + k]; lib[k] = si[(tid + stride) * TOPK + k];
            }
            int pa = 0, pb = 0;
            #pragma unroll
            for (int k = 0; k < TOPK; ++k) {
                bool takeA = (la[pa] > lb[pb]) ||
                             (la[pa] == lb[pb] && lia[pa] <= lib[pb]);
                if (takeA) { ov[k] = la[pa]; oi[k] = lia[pa]; ++pa; }
                else       { ov[k] = lb[pb]; oi[k] = lib[pb]; ++pb; }
            }
            #pragma unroll
            for (int k = 0; k < TOPK; ++k) { sv[tid * TOPK + k] = ov[k]; si[tid * TOPK + k] = oi[k]; }
        }
    }
    __syncthreads();

    // every thread reads the final top-8 and gathers
    float wt[TOPK]; const float* rowp[TOPK];
    float den = 0.f;
    #pragma unroll
    for (int k = 0; k < TOPK; ++k) {
        wt[k] = sv[k];
        int m = si[k];
        rowp[k] = (m < S_SHOT) ? (sup + (m * W_WAY + w) * D_DIM)
                               : (mem + (size_t)(m - S_SHOT) * D_DIM);
        den += wt[k];
    }
    float rden = 1.0f / den;
    for (int d = tid; d < D_DIM; d += FT_THREADS) {
        float acc = 0.f;
        #pragma unroll
        for (int k = 0; k < TOPK; ++k) acc += wt[k] * rowp[k][d];
        out[w * D_DIM + d] = acc * rden;
    }
}

// ---------------------------------------------------------------------------
extern "C" void kernel_launch(void* const* d_in, const int* in_sizes, int n_in,
                              void* d_out, int out_size) {
    const float* sup = (const float*)d_in[0];   // [1,5,5,640]
    const float* mem = (const float*)d_in[1];   // [M,640]
    float* out = (float*)d_out;                 // [1,5,640]

    int M = in_sizes[1] / D_DIM;
    if (M > M_MAX) M = M_MAX;

    prep_kernel<<<1, 1024>>>(sup);
    sim_kernel<<<SIM_BLOCKS, SIM_THREADS>>>(mem, M);
    final_kernel<<<W_WAY, FT_THREADS>>>(sup, mem, out);
}